// round 2
// baseline (speedup 1.0000x reference)
#include <cuda_runtime.h>
#include <math.h>

#define B_  8
#define T_  4096
#define D_  1024
#define D4_ 256
#define A_  32
#define S_  16
#define H_  256
#define W_  241
#define NP_ 256
#define RB_ 8

// Per-(pair,rowblock) partial column sums + per-rowblock shift partials.
__device__ float g_partial[NP_][RB_][D_];
__device__ float g_shiftp[NP_][RB_];

__constant__ int c_alias[64] = {
  -1,-1,-1,-1,-1,-1,-1,-1,-1,-1,   // 0-9
  -1,11,-1,11,-1,-1,11,-1,-1,-1,   // 10-19
  -1,21,21,21,-1,-1,-1,-1,-1,-1,   // 20-29
  -1,31,31,31,-1,-1,-1,-1,-1,-1,   // 30-39
  -1,41,41,41,41,-1,-1,-1,-1,-1,   // 40-49
  -1,51,51,51,-1,-1,-1,-1,-1,-1,   // 50-59
  -1,-1,-1,-1                      // 60-63
};

// ---------------------------------------------------------------------------
// Kernel 1: heavy reduction over future = hidden[b, start:start+H, :]
// grid = (256 pairs, 8 rowblocks), block = 256 threads (8 warps)
// Each warp owns 4 whole rows of 1024 floats, read as float4 (LDG.128).
// Per-row sq-norm -> warp shuffle reduce; column sums accumulate in
// registers, spill to per-warp smem float4 arrays (conflict-free), then a
// single cross-warp sum writes the per-rowblock partials to global scratch.
// ---------------------------------------------------------------------------
__global__ void __launch_bounds__(256) k_reduce(
    const float* __restrict__ hidden, const float* __restrict__ anchor,
    const int* __restrict__ anchor_end) {
  __shared__ float4 sanchor[D4_];
  __shared__ float4 swarp[8][D4_];      // 32 KB
  __shared__ float sShiftW[8];
  const int p = blockIdx.x, rb = blockIdx.y;
  const int tid = threadIdx.x;
  const int b = p >> 5;
  const int start = anchor_end[p] + 1;

  const float4* anchor4 = (const float4*)(anchor + (size_t)p * D_);
  for (int i = tid; i < D4_; i += 256) sanchor[i] = __ldg(anchor4 + i);
  __syncthreads();

  const int warp = tid >> 5, lane = tid & 31;
  float4 colacc[8];
#pragma unroll
  for (int j = 0; j < 8; j++) colacc[j] = make_float4(0.f, 0.f, 0.f, 0.f);
  float shiftsum = 0.f;

  const float4* base4 =
      (const float4*)(hidden + ((size_t)b * T_ + start + rb * 32) * D_);
#pragma unroll
  for (int r = 0; r < 4; r++) {
    const float4* row4 = base4 + (size_t)(warp + 8 * r) * D4_;
    float ssq = 0.f;
#pragma unroll
    for (int j = 0; j < 8; j++) {
      float4 x = __ldg(row4 + lane + 32 * j);
      float4 a = sanchor[lane + 32 * j];
      colacc[j].x += x.x; colacc[j].y += x.y;
      colacc[j].z += x.z; colacc[j].w += x.w;
      float d0 = x.x - a.x, d1 = x.y - a.y, d2 = x.z - a.z, d3 = x.w - a.w;
      ssq += d0 * d0 + d1 * d1 + d2 * d2 + d3 * d3;
    }
#pragma unroll
    for (int o = 16; o; o >>= 1) ssq += __shfl_xor_sync(0xffffffffu, ssq, o);
    shiftsum += sqrtf(ssq);
  }
#pragma unroll
  for (int j = 0; j < 8; j++) swarp[warp][lane + 32 * j] = colacc[j];
  if (lane == 0) sShiftW[warp] = shiftsum;
  __syncthreads();

  // Cross-warp combine: thread i owns float4 column i.
  {
    float4 s = swarp[0][tid];
#pragma unroll
    for (int w = 1; w < 8; w++) {
      float4 t = swarp[w][tid];
      s.x += t.x; s.y += t.y; s.z += t.z; s.w += t.w;
    }
    ((float4*)g_partial[p][rb])[tid] = s;
  }
  if (tid == 0) {
    float sh = 0.f;
#pragma unroll
    for (int w = 0; w < 8; w++) sh += sShiftW[w];
    g_shiftp[p][rb] = sh;
  }
}

// ---------------------------------------------------------------------------
// Block reductions (blockDim = 256, 8 warps)
// ---------------------------------------------------------------------------
__device__ __forceinline__ float bsum(float v, volatile float* sred) {
#pragma unroll
  for (int o = 16; o; o >>= 1) v += __shfl_xor_sync(0xffffffffu, v, o);
  __syncthreads();
  if ((threadIdx.x & 31) == 0) sred[threadIdx.x >> 5] = v;
  __syncthreads();
  float t = 0.f;
#pragma unroll
  for (int i = 0; i < 8; i++) t += sred[i];
  return t;
}
__device__ __forceinline__ float bmax(float v, volatile float* sred) {
#pragma unroll
  for (int o = 16; o; o >>= 1) v = fmaxf(v, __shfl_xor_sync(0xffffffffu, v, o));
  __syncthreads();
  if ((threadIdx.x & 31) == 0) sred[threadIdx.x >> 5] = v;
  __syncthreads();
  float t = sred[0];
#pragma unroll
  for (int i = 1; i < 8; i++) t = fmaxf(t, sred[i]);
  return t;
}

// ---------------------------------------------------------------------------
// Kernel 2: finalize — cosine sim + all token/window logic + outputs.
// grid = 256 pairs, block = 256 threads (one thread per window, W=241).
// ---------------------------------------------------------------------------
__global__ void __launch_bounds__(256) k_final(
    const float* __restrict__ anchor, const int* __restrict__ ids,
    const int* __restrict__ anchor_end, float* __restrict__ out) {
  __shared__ float sred[8];
  __shared__ int ftok[H_];
  __shared__ int sspan[S_];
  __shared__ int salias[64];
  __shared__ int s_root, s_hasT;
  __shared__ float s_invden;
  __shared__ unsigned long long s_dmask, s_cmask;

  const int p = blockIdx.x;
  const int b = p >> 5;
  const int tid = threadIdx.x;
  const int ae = anchor_end[p];
  const int start = ae + 1;

  ftok[tid] = ids[b * T_ + start + tid];
  if (tid < S_) sspan[tid] = ids[b * T_ + ae - (S_ - 1) + tid];
  if (tid < 64) salias[tid] = c_alias[tid];

  // mean_future dot products
  float dot = 0.f, nm = 0.f, na = 0.f;
  for (int d = tid; d < D_; d += 256) {
    float s = 0.f;
#pragma unroll
    for (int rb = 0; rb < RB_; rb++) s += g_partial[p][rb][d];
    float m = s * (1.f / H_);
    float av = anchor[(size_t)p * D_ + d];
    dot += m * av;
    nm += m * m;
    na += av * av;
  }
  __syncthreads();
  dot = bsum(dot, sred);
  nm = bsum(nm, sred);
  na = bsum(na, sred);
  const float eps = 1e-8f;
  float sim = dot / (fmaxf(sqrtf(na), eps) * fmaxf(sqrtf(nm), eps));
  float hidden_c = fmaxf(0.f, (1.f - sim) * 0.5f);

  // token_c
  int atok = sspan[S_ - 1];
  float tcnt = (ftok[tid] == atok) ? 1.f : 0.f;
  tcnt = bsum(tcnt, sred);
  float token_c = 1.f - tcnt * (1.f / H_);

  // span analysis (cheap, single thread)
  if (tid == 0) {
    unsigned long long dm = 0ull;
    int denom = 0;
    for (int s = 0; s < S_; s++) {
      unsigned long long bit = 1ull << sspan[s];
      if (!(dm & bit)) { dm |= bit; denom++; }
    }
    int counts[S_], maxc = 0;
    for (int s = 0; s < S_; s++) {
      int c = 0;
      for (int s2 = 0; s2 < S_; s2++) c += (sspan[s] == sspan[s2]);
      counts[s] = c;
      maxc = max(maxc, c);
    }
    int mode = 64;
    for (int s = 0; s < S_; s++)
      if (counts[s] == maxc) mode = min(mode, sspan[s]);
    int root = -1;
    for (int s = 0; s < S_; s++) {
      int al = salias[sspan[s]];
      if (al >= 0) { root = al; break; }
    }
    if (root < 0) root = mode;
    unsigned long long cm = 0ull;
    switch (root) {
      case 11: cm = (1ull<<11)|(1ull<<13)|(1ull<<16); break;
      case 21: cm = (1ull<<14)|(1ull<<15)|(1ull<<21)|(1ull<<22)|(1ull<<23); break;
      case 31: cm = (1ull<<15)|(1ull<<31)|(1ull<<32)|(1ull<<33); break;
      case 41: cm = (1ull<<41)|(1ull<<42)|(1ull<<43)|(1ull<<44); break;
      case 51: cm = (1ull<<15)|(1ull<<51)|(1ull<<52)|(1ull<<53); break;
      default: break;
    }
    s_root = root;
    s_cmask = cm;
    s_hasT = (cm != 0ull) ? 1 : 0;
    s_dmask = dm;
    s_invden = 1.f / (float)denom;
  }
  __syncthreads();

  const int root = s_root;
  const unsigned long long cmask = s_cmask, dmask = s_dmask;
  const int hasT = s_hasT;
  const float invden = s_invden;

  float sims = 0.f, rp = 0.f, regime = 0.f, hit = 0.f;
  float simmax = -1e30f;
  if (tid < W_) {
    float ex = 0.f, pos = 0.f, ac = 0.f, hd = 0.f;
    unsigned long long wm = 0ull;
#pragma unroll
    for (int s = 0; s < S_; s++) {
      int tok = ftok[tid + s];
      wm |= 1ull << tok;
      float eq = (tok == sspan[s]) ? 1.f : 0.f;
      ex += eq;
      pos += eq * (1.0f - 0.04f * (float)s);
      rp += (tok == root) ? 1.f : 0.f;
      ac += (salias[tok] == root) ? 1.f : 0.f;
      hd += (float)((cmask >> tok) & 1ull);
    }
    ex *= (1.f / S_);
    pos *= (1.f / 11.2f);
    rp *= (1.f / S_);
    ac *= (1.f / S_);
    hd *= (1.f / S_);
    float ov = (float)__popcll(wm & dmask) * invden;
    regime = hasT ? (0.55f * hd + 0.2f * ov + 0.15f * ac + 0.1f * rp)
                  : (0.45f * ex + 0.3f * ov + 0.1f * ac + 0.15f * rp);
    sims = 0.25f * ex + 0.15f * ov + 0.35f * pos + 0.25f * regime;
    simmax = sims;
    hit = (sims >= 0.6f) ? 1.f : 0.f;
  }
  float sum_sims = bsum(sims, sred);
  float sum_rp   = bsum(rp, sred);
  float sum_reg  = bsum(regime, sred);
  float sum_hit  = bsum(hit, sred);
  float best     = bmax(simmax, sred);

  if (tid == 0) {
    const float invW = 1.f / (float)W_;
    float msims = sum_sims * invW;
    float mrp = sum_rp * invW;
    float mrc = sum_reg * invW;
    float dmass = sum_hit * invW;
    float dcoh = 0.6f * msims + 0.25f * mrp + 0.15f * mrc;
    float pattern_c = 1.f - (0.6f * best + 0.2f * mrp + 0.2f * mrc);
    float contr = 0.2f * hidden_c + 0.2f * token_c + 0.6f * pattern_c;
    contr = fminf(fmaxf(contr, 0.f), 1.f);
    float sh = 0.f;
#pragma unroll
    for (int rb = 0; rb < RB_; rb++) sh += g_shiftp[p][rb];
    sh *= (1.f / H_);
    out[0 * NP_ + p] = contr;
    out[1 * NP_ + p] = sh;
    out[2 * NP_ + p] = sim;
    out[3 * NP_ + p] = hidden_c;
    out[4 * NP_ + p] = token_c;
    out[5 * NP_ + p] = pattern_c;
    out[6 * NP_ + p] = dmass;
    out[7 * NP_ + p] = dcoh;
  }
}

extern "C" void kernel_launch(void* const* d_in, const int* in_sizes, int n_in,
                              void* d_out, int out_size) {
  const float* hidden = (const float*)d_in[0];
  const float* anchor = (const float*)d_in[1];
  const int* ids = (const int*)d_in[2];
  const int* ae = (const int*)d_in[3];
  float* out = (float*)d_out;
  dim3 g1(NP_, RB_);
  k_reduce<<<g1, 256>>>(hidden, anchor, ae);
  k_final<<<NP_, 256>>>(anchor, ids, ae, out);
}